// round 9
// baseline (speedup 1.0000x reference)
#include <cuda_runtime.h>
#include <cstdint>

#define TSTEPS 256
#define HSZ 50
#define ISZ 7
#define EPB 32
#define NTHREADS 512
#define NBLOCKS 128

typedef unsigned long long u64;

// smem layout (float offsets)
#define OFF_WX0 0        // [7][50][4]   1400
#define OFF_WH0 1400     // [50][50][4] 10000
#define OFF_WI1 11400    // [50][50][4] 10000
#define OFF_WH1 21400    // [50][50][4] 10000
#define OFF_B0  31400    // [50][4]       200
#define OFF_B1  31600    // [50][4]       200
#define OFF_WFC 31800    // [7][50]       350
#define OFF_BFC 32152    // [8]             8
#define OFF_XS  32160    // [2][7][32]    448
#define OFF_H0  32608    // [2][50][32]  3200
#define OFF_H1  35808    // [2][50][32]  3200
#define SMEM_FLOATS 39008

__device__ __forceinline__ u64 pk2(float lo, float hi) {
    u64 r; asm("mov.b64 %0,{%1,%2};" : "=l"(r) : "f"(lo), "f"(hi)); return r;
}
__device__ __forceinline__ void upk2(float& lo, float& hi, u64 v) {
    asm("mov.b64 {%0,%1},%2;" : "=f"(lo), "=f"(hi) : "l"(v));
}
__device__ __forceinline__ void fma2(u64& c, u64 a, u64 b) {
    asm("fma.rn.f32x2 %0,%1,%2,%0;" : "+l"(c) : "l"(a), "l"(b));
}

__device__ __forceinline__ float sigm(float v) {
    return __fdividef(1.f, 1.f + __expf(-v));
}
__device__ __forceinline__ float tanh_f(float v) {
    return __fdividef(2.f, 1.f + __expf(-2.f * v)) - 1.f;
}

// N-step matvec accumulate, EPT=4 variant.
// Wp: packed weights [(k*50+j)*4 + gate]; one LDS.128 per k.
// hb: operand base pre-offset by this thread's g*4 (row stride 32 floats);
//     one LDS.128 per k yields 4 elements = 2 u64 pairs.
// acc[gate*2 + p]: pair p covers elements 2p, 2p+1.
template<int N>
__device__ __forceinline__ void mvN(const float* __restrict__ Wp,
                                    const float* __restrict__ hb,
                                    int j, u64 acc[8]) {
    #pragma unroll 10
    for (int k = 0; k < N; k++) {
        const float4 w4 = *reinterpret_cast<const float4*>(Wp + (k * HSZ + j) * 4);
        const u64 wi = pk2(w4.x, w4.x), wf = pk2(w4.y, w4.y);
        const u64 wg = pk2(w4.z, w4.z), wo = pk2(w4.w, w4.w);
        const ulonglong2 hh = *reinterpret_cast<const ulonglong2*>(hb + k * EPB);
        fma2(acc[0], wi, hh.x); fma2(acc[1], wi, hh.y);
        fma2(acc[2], wf, hh.x); fma2(acc[3], wf, hh.y);
        fma2(acc[4], wg, hh.x); fma2(acc[5], wg, hh.y);
        fma2(acc[6], wo, hh.x); fma2(acc[7], wo, hh.y);
    }
}

__device__ __forceinline__ void gates4(const u64 acc[8], float c[4], float hn[4]) {
    #pragma unroll
    for (int p = 0; p < 2; p++) {
        float i0, i1, f0, f1, g0, g1, o0, o1;
        upk2(i0, i1, acc[p]);
        upk2(f0, f1, acc[2 + p]);
        upk2(g0, g1, acc[4 + p]);
        upk2(o0, o1, acc[6 + p]);
        const int e = 2 * p;
        c[e]     = sigm(f0) * c[e]     + sigm(i0) * tanh_f(g0);
        c[e + 1] = sigm(f1) * c[e + 1] + sigm(i1) * tanh_f(g1);
        hn[e]     = sigm(o0) * tanh_f(c[e]);
        hn[e + 1] = sigm(o1) * tanh_f(c[e + 1]);
    }
}

__global__ __launch_bounds__(NTHREADS, 1)
void lstm2_fused_v5(const float* __restrict__ x,
                    const float* __restrict__ w_ih0, const float* __restrict__ w_hh0,
                    const float* __restrict__ b_ih0, const float* __restrict__ b_hh0,
                    const float* __restrict__ w_ih1, const float* __restrict__ w_hh1,
                    const float* __restrict__ b_ih1, const float* __restrict__ b_hh1,
                    const float* __restrict__ w_fc,  const float* __restrict__ b_fc,
                    float* __restrict__ out)
{
    extern __shared__ float sm[];
    const int tid = threadIdx.x;
    const int blk = blockIdx.x;

    // ---- stage weights to shared, packed/transposed [k][j][i,f,g,o] ----
    for (int i = tid; i < HSZ * HSZ * 4; i += NTHREADS) {       // 10000 each
        const int k = i / 200, r = i % 200;
        const int j = r >> 2, gi = r & 3;
        const int src = (gi * HSZ + j) * HSZ + k;
        sm[OFF_WH0 + i] = w_hh0[src];
        sm[OFF_WI1 + i] = w_ih1[src];
        sm[OFF_WH1 + i] = w_hh1[src];
    }
    for (int i = tid; i < ISZ * HSZ * 4; i += NTHREADS) {       // 1400
        const int k = i / 200, r = i % 200;
        const int j = r >> 2, gi = r & 3;
        sm[OFF_WX0 + i] = w_ih0[(gi * HSZ + j) * ISZ + k];
    }
    for (int i = tid; i < 200; i += NTHREADS) {
        const int j = i >> 2, gi = i & 3;
        sm[OFF_B0 + i] = b_ih0[gi * HSZ + j] + b_hh0[gi * HSZ + j];
        sm[OFF_B1 + i] = b_ih1[gi * HSZ + j] + b_hh1[gi * HSZ + j];
    }
    for (int i = tid; i < ISZ * HSZ; i += NTHREADS) sm[OFF_WFC + i] = w_fc[i];
    if (tid < ISZ) sm[OFF_BFC + tid] = b_fc[tid];
    // zero both h buffers
    for (int i = tid; i < 2 * HSZ * EPB; i += NTHREADS) {
        sm[OFF_H0 + i] = 0.f;
        sm[OFF_H1 + i] = 0.f;
    }
    // preload x for t=0 into xs buffer 0: xs[k][e]
    if (tid < ISZ * EPB) {
        const int e = tid & 31, kx = tid >> 5;
        sm[OFF_XS + kx * 32 + e] = x[(size_t)(blk * EPB + e) * (TSTEPS * ISZ) + kx];
    }
    __syncthreads();

    const int j = tid >> 3;          // cell 0..63 (active < 50)
    const int g = tid & 7;           // element group, 4 elems each
    const bool act = (j < HSZ);
    const int go = g * 4;            // element offset within block (16B aligned)

    float4 b0v = make_float4(0.f, 0.f, 0.f, 0.f), b1v = b0v;
    if (act) {
        b0v = *reinterpret_cast<const float4*>(sm + OFF_B0 + j * 4);
        b1v = *reinterpret_cast<const float4*>(sm + OFF_B1 + j * 4);
    }

    // per-step x loader: tid<224, kx = tid>>5, e = tid&31
    const float* xp = x;
    if (tid < EPB * ISZ)
        xp = x + (size_t)(blk * EPB + (tid & 31)) * (TSTEPS * ISZ) + (tid >> 5);

    float c0[4] = {0.f, 0.f, 0.f, 0.f};
    float c1[4] = {0.f, 0.f, 0.f, 0.f};
    u64 acc[8];

    int buf = 0;
    for (int t = 0; t < TSTEPS; t++) {
        // prefetch x_{t+1} (lands during compute)
        float xv = 0.f;
        if (tid < EPB * ISZ && t + 1 < TSTEPS) xv = xp[(t + 1) * ISZ];

        // ---- layer 0 ----
        if (act) {
            acc[0] = acc[1] = pk2(b0v.x, b0v.x);
            acc[2] = acc[3] = pk2(b0v.y, b0v.y);
            acc[4] = acc[5] = pk2(b0v.z, b0v.z);
            acc[6] = acc[7] = pk2(b0v.w, b0v.w);
            mvN<HSZ>(sm + OFF_WH0, sm + OFF_H0 + buf * 1600 + go, j, acc);
            mvN<ISZ>(sm + OFF_WX0, sm + OFF_XS + buf * 224  + go, j, acc);
            float hn[4];
            gates4(acc, c0, hn);
            *reinterpret_cast<float4*>(sm + OFF_H0 + (buf ^ 1) * 1600 + j * EPB + go) =
                make_float4(hn[0], hn[1], hn[2], hn[3]);
        }
        __syncthreads();   // A: new h0 visible

        // ---- layer 1 ----
        if (act) {
            acc[0] = acc[1] = pk2(b1v.x, b1v.x);
            acc[2] = acc[3] = pk2(b1v.y, b1v.y);
            acc[4] = acc[5] = pk2(b1v.z, b1v.z);
            acc[6] = acc[7] = pk2(b1v.w, b1v.w);
            mvN<HSZ>(sm + OFF_WI1, sm + OFF_H0 + (buf ^ 1) * 1600 + go, j, acc);
            mvN<HSZ>(sm + OFF_WH1, sm + OFF_H1 + buf * 1600 + go, j, acc);
            float hn[4];
            gates4(acc, c1, hn);
            *reinterpret_cast<float4*>(sm + OFF_H1 + (buf ^ 1) * 1600 + j * EPB + go) =
                make_float4(hn[0], hn[1], hn[2], hn[3]);
        }
        if (tid < EPB * ISZ) sm[OFF_XS + (buf ^ 1) * 224 + tid] = xv;
        __syncthreads();   // B: new h1 + new x visible
        buf ^= 1;
    }

    // ---- FC head: out[e][j] = b_fc[j] + sum_k w_fc[j][k] * h2[e][k] ----
    if (j < ISZ) {
        const float* h2 = sm + OFF_H1 + buf * 1600 + go;
        const float bv = sm[OFF_BFC + j];
        float s[4] = {bv, bv, bv, bv};
        #pragma unroll 10
        for (int k = 0; k < HSZ; k++) {
            const float wv = sm[OFF_WFC + j * HSZ + k];
            #pragma unroll
            for (int e = 0; e < 4; e++) s[e] = fmaf(wv, h2[k * EPB + e], s[e]);
        }
        #pragma unroll
        for (int e = 0; e < 4; e++)
            out[(size_t)(blk * EPB + go + e) * ISZ + j] = s[e];
    }
}

extern "C" void kernel_launch(void* const* d_in, const int* in_sizes, int n_in,
                              void* d_out, int out_size)
{
    const float* x     = (const float*)d_in[0];
    const float* w_ih0 = (const float*)d_in[1];
    const float* w_hh0 = (const float*)d_in[2];
    const float* b_ih0 = (const float*)d_in[3];
    const float* b_hh0 = (const float*)d_in[4];
    const float* w_ih1 = (const float*)d_in[5];
    const float* w_hh1 = (const float*)d_in[6];
    const float* b_ih1 = (const float*)d_in[7];
    const float* b_hh1 = (const float*)d_in[8];
    const float* w_fc  = (const float*)d_in[9];
    const float* b_fc  = (const float*)d_in[10];
    float* out = (float*)d_out;

    const size_t smem_bytes = SMEM_FLOATS * sizeof(float);
    cudaFuncSetAttribute(lstm2_fused_v5,
                         cudaFuncAttributeMaxDynamicSharedMemorySize,
                         (int)smem_bytes);

    lstm2_fused_v5<<<NBLOCKS, NTHREADS, smem_bytes>>>(
        x, w_ih0, w_hh0, b_ih0, b_hh0,
        w_ih1, w_hh1, b_ih1, b_hh1,
        w_fc, b_fc, out);
}

// round 10
// speedup vs baseline: 2.3081x; 2.3081x over previous
#include <cuda_runtime.h>
#include <cstdint>

#define TSTEPS 256
#define HSZ 50
#define ISZ 7
#define EPB 32
#define NTH 512
#define NBLK 128
#define MT 13          // number of m16 tiles (208 gate rows >= 200)
#define K0C 8          // layer0 K chunks (K=64: 50 h + 7 x + 7 zero)
#define K1C 13         // layer1 K chunks (K=104: 50 h0 + 50 h1 + 4 zero)
#define SG 36          // gates buffer row stride
#define S0 68          // hT0 row stride (32 rows x 68)
#define S1 108         // hT1 / Wsm1 row stride

// smem float offsets
#define OFF_W1 0                   // [208][108] = 22464
#define OFF_G  22464               // [208][36]  = 7488
#define OFF_T0 29952               // [32][68]   = 2176
#define OFF_T1 32128               // [32][108]  = 3456
#define OFF_B0 35584               // [208]
#define OFF_B1 35792               // [208]
#define SMEMF  36000               // 144000 bytes

__device__ __forceinline__ float sigm(float v) {
    return __fdividef(1.f, 1.f + __expf(-v));
}
__device__ __forceinline__ float tanh_f(float v) {
    return __fdividef(2.f, 1.f + __expf(-2.f * v)) - 1.f;
}
__device__ __forceinline__ uint32_t tf32u(float f) {
    uint32_t u; asm("cvt.rna.tf32.f32 %0, %1;" : "=r"(u) : "f"(f)); return u;
}
__device__ __forceinline__ float tf32f(float f) {
    return __uint_as_float(tf32u(f));
}
__device__ __forceinline__ void mma_tf32(float d[4], const uint32_t a[4],
                                         uint32_t b0, uint32_t b1) {
    asm volatile(
        "mma.sync.aligned.m16n8k8.row.col.f32.tf32.tf32.f32 "
        "{%0,%1,%2,%3}, {%4,%5,%6,%7}, {%8,%9}, {%0,%1,%2,%3};"
        : "+f"(d[0]), "+f"(d[1]), "+f"(d[2]), "+f"(d[3])
        : "r"(a[0]), "r"(a[1]), "r"(a[2]), "r"(a[3]), "r"(b0), "r"(b1));
}

// layer0 A element (gate-row r in [j][i,f,g,o] order, col c over [h(50)|x(7)|0])
__device__ __forceinline__ float w0val(const float* __restrict__ wih0,
                                       const float* __restrict__ whh0,
                                       int r, int c) {
    if (r >= 200) return 0.f;
    const int j = r >> 2, gi = r & 3;
    if (c < 50) return whh0[(gi * 50 + j) * 50 + c];
    if (c < 57) return wih0[(gi * 50 + j) * 7 + (c - 50)];
    return 0.f;
}

__global__ __launch_bounds__(NTH, 1)
void lstm2_tc_v6(const float* __restrict__ x,
                 const float* __restrict__ w_ih0, const float* __restrict__ w_hh0,
                 const float* __restrict__ b_ih0, const float* __restrict__ b_hh0,
                 const float* __restrict__ w_ih1, const float* __restrict__ w_hh1,
                 const float* __restrict__ b_ih1, const float* __restrict__ b_hh1,
                 const float* __restrict__ w_fc,  const float* __restrict__ b_fc,
                 float* __restrict__ out)
{
    extern __shared__ float sm[];
    const int tid  = threadIdx.x;
    const int blk  = blockIdx.x;
    const int wid  = tid >> 5;
    const int lane = tid & 31;
    const int gid  = lane >> 2;     // groupID 0..7
    const int t4   = lane & 3;      // threadID in group

    // ---- stage layer1 weights [208][104] (tf32) ----
    for (int i = tid; i < 208 * 104; i += NTH) {
        const int r = i / 104, k = i % 104;
        float v = 0.f;
        if (r < 200) {
            const int j = r >> 2, gi = r & 3;
            if (k < 50)       v = w_ih1[(gi * 50 + j) * 50 + k];
            else if (k < 100) v = w_hh1[(gi * 50 + j) * 50 + (k - 50)];
        }
        sm[OFF_W1 + r * S1 + k] = tf32f(v);
    }
    // biases (fp32, accumulator init)
    for (int i = tid; i < 208; i += NTH) {
        float v0 = 0.f, v1 = 0.f;
        if (i < 200) {
            const int j = i >> 2, gi = i & 3;
            v0 = b_ih0[gi * 50 + j] + b_hh0[gi * 50 + j];
            v1 = b_ih1[gi * 50 + j] + b_hh1[gi * 50 + j];
        }
        sm[OFF_B0 + i] = v0;
        sm[OFF_B1 + i] = v1;
    }
    // zero operand buffers
    for (int i = tid; i < 32 * S0; i += NTH) sm[OFF_T0 + i] = 0.f;
    for (int i = tid; i < 32 * S1; i += NTH) sm[OFF_T1 + i] = 0.f;
    __syncthreads();
    // x(t=0) into hT0 cols 50..56
    if (tid < 224) {
        const int e = tid / 7, kx = tid % 7;
        sm[OFF_T0 + e * S0 + 50 + kx] =
            tf32f(x[(size_t)(blk * EPB + e) * (TSTEPS * ISZ) + kx]);
    }
    __syncthreads();

    // ---- layer0 A-fragments resident in registers ----
    const int M0 = wid * 16;
    uint32_t wa0[K0C][4];
    if (wid < MT) {
        const int r0 = M0 + gid, r1 = r0 + 8;
        #pragma unroll
        for (int kc = 0; kc < K0C; kc++) {
            const int c0 = kc * 8 + t4, c1 = c0 + 4;
            wa0[kc][0] = tf32u(w0val(w_ih0, w_hh0, r0, c0));
            wa0[kc][1] = tf32u(w0val(w_ih0, w_hh0, r1, c0));
            wa0[kc][2] = tf32u(w0val(w_ih0, w_hh0, r0, c1));
            wa0[kc][3] = tf32u(w0val(w_ih0, w_hh0, r1, c1));
        }
    }

    // activation thread mapping: tid<400 -> (j = tid>>3, g = tid&7) owns elems 4g..4g+3
    const int jj = tid >> 3;
    const int gg = tid & 7;
    float c0s[4] = {0.f, 0.f, 0.f, 0.f};
    float c1s[4] = {0.f, 0.f, 0.f, 0.f};

    const float* xp = x;
    if (tid < 224)
        xp = x + (size_t)(blk * EPB + tid / 7) * (TSTEPS * ISZ) + (tid % 7);

    for (int t = 0; t < TSTEPS; t++) {
        float xv = 0.f;
        if (tid < 224 && t + 1 < TSTEPS) xv = xp[(t + 1) * ISZ];

        // ============ MMA layer 0 ============
        if (wid < MT) {
            float acc[4][4];
            const float bl = sm[OFF_B0 + M0 + gid];
            const float bh = sm[OFF_B0 + M0 + 8 + gid];
            #pragma unroll
            for (int n = 0; n < 4; n++) {
                acc[n][0] = bl; acc[n][1] = bl; acc[n][2] = bh; acc[n][3] = bh;
            }
            #pragma unroll
            for (int kc = 0; kc < K0C; kc++) {
                #pragma unroll
                for (int n = 0; n < 4; n++) {
                    const float* bp = sm + OFF_T0 + (n * 8 + gid) * S0 + kc * 8 + t4;
                    mma_tf32(acc[n], wa0[kc],
                             __float_as_uint(bp[0]), __float_as_uint(bp[4]));
                }
            }
            #pragma unroll
            for (int n = 0; n < 4; n++) {
                *reinterpret_cast<float2*>(sm + OFF_G + (M0 + gid) * SG + n * 8 + t4 * 2) =
                    make_float2(acc[n][0], acc[n][1]);
                *reinterpret_cast<float2*>(sm + OFF_G + (M0 + 8 + gid) * SG + n * 8 + t4 * 2) =
                    make_float2(acc[n][2], acc[n][3]);
            }
        }
        __syncthreads();

        // ============ activation layer 0 ============
        if (tid < 400) {
            const float* gb = sm + OFF_G + (jj * 4) * SG + gg * 4;
            const float4 vi = *reinterpret_cast<const float4*>(gb);
            const float4 vf = *reinterpret_cast<const float4*>(gb + SG);
            const float4 vg = *reinterpret_cast<const float4*>(gb + 2 * SG);
            const float4 vo = *reinterpret_cast<const float4*>(gb + 3 * SG);
            float hv[4];
            {
                const float* iv = &vi.x; const float* fv = &vf.x;
                const float* gv = &vg.x; const float* ov = &vo.x;
                #pragma unroll
                for (int e = 0; e < 4; e++) {
                    c0s[e] = sigm(fv[e]) * c0s[e] + sigm(iv[e]) * tanh_f(gv[e]);
                    hv[e]  = sigm(ov[e]) * tanh_f(c0s[e]);
                }
            }
            #pragma unroll
            for (int e = 0; e < 4; e++) {
                const float ht = tf32f(hv[e]);
                sm[OFF_T0 + (gg * 4 + e) * S0 + jj] = ht;   // layer0 h for t+1
                sm[OFF_T1 + (gg * 4 + e) * S1 + jj] = ht;   // layer1 input rows 0-49
            }
        }
        if (tid < 224) sm[OFF_T0 + (tid / 7) * S0 + 50 + tid % 7] = tf32f(xv);
        __syncthreads();

        // ============ MMA layer 1 ============
        if (wid < MT) {
            float acc[4][4];
            const float bl = sm[OFF_B1 + M0 + gid];
            const float bh = sm[OFF_B1 + M0 + 8 + gid];
            #pragma unroll
            for (int n = 0; n < 4; n++) {
                acc[n][0] = bl; acc[n][1] = bl; acc[n][2] = bh; acc[n][3] = bh;
            }
            #pragma unroll
            for (int kc = 0; kc < K1C; kc++) {
                const float* ap = sm + OFF_W1 + (M0 + gid) * S1 + kc * 8 + t4;
                uint32_t a[4];
                a[0] = __float_as_uint(ap[0]);
                a[1] = __float_as_uint(ap[8 * S1]);
                a[2] = __float_as_uint(ap[4]);
                a[3] = __float_as_uint(ap[8 * S1 + 4]);
                #pragma unroll
                for (int n = 0; n < 4; n++) {
                    const float* bp = sm + OFF_T1 + (n * 8 + gid) * S1 + kc * 8 + t4;
                    mma_tf32(acc[n], a,
                             __float_as_uint(bp[0]), __float_as_uint(bp[4]));
                }
            }
            #pragma unroll
            for (int n = 0; n < 4; n++) {
                *reinterpret_cast<float2*>(sm + OFF_G + (M0 + gid) * SG + n * 8 + t4 * 2) =
                    make_float2(acc[n][0], acc[n][1]);
                *reinterpret_cast<float2*>(sm + OFF_G + (M0 + 8 + gid) * SG + n * 8 + t4 * 2) =
                    make_float2(acc[n][2], acc[n][3]);
            }
        }
        __syncthreads();

        // ============ activation layer 1 ============
        if (tid < 400) {
            const float* gb = sm + OFF_G + (jj * 4) * SG + gg * 4;
            const float4 vi = *reinterpret_cast<const float4*>(gb);
            const float4 vf = *reinterpret_cast<const float4*>(gb + SG);
            const float4 vg = *reinterpret_cast<const float4*>(gb + 2 * SG);
            const float4 vo = *reinterpret_cast<const float4*>(gb + 3 * SG);
            const float* iv = &vi.x; const float* fv = &vf.x;
            const float* gv = &vg.x; const float* ov = &vo.x;
            #pragma unroll
            for (int e = 0; e < 4; e++) {
                c1s[e] = sigm(fv[e]) * c1s[e] + sigm(iv[e]) * tanh_f(gv[e]);
                const float h1 = sigm(ov[e]) * tanh_f(c1s[e]);
                sm[OFF_T1 + (gg * 4 + e) * S1 + 50 + jj] = tf32f(h1);  // rows 50-99 for t+1
            }
        }
        __syncthreads();
    }

    // ---- FC head: out[e][i] = b_fc[i] + sum_k w_fc[i][k] * h1[e][k] ----
    if (tid < 224) {
        const int i = tid % 7, e = tid / 7;
        float s = b_fc[i];
        #pragma unroll 10
        for (int k = 0; k < HSZ; k++)
            s = fmaf(w_fc[i * 50 + k], sm[OFF_T1 + e * S1 + 50 + k], s);
        out[(size_t)(blk * EPB + e) * ISZ + i] = s;
    }
}

extern "C" void kernel_launch(void* const* d_in, const int* in_sizes, int n_in,
                              void* d_out, int out_size)
{
    const float* x     = (const float*)d_in[0];
    const float* w_ih0 = (const float*)d_in[1];
    const float* w_hh0 = (const float*)d_in[2];
    const float* b_ih0 = (const float*)d_in[3];
    const float* b_hh0 = (const float*)d_in[4];
    const float* w_ih1 = (const float*)d_in[5];
    const float* w_hh1 = (const float*)d_in[6];
    const float* b_ih1 = (const float*)d_in[7];
    const float* b_hh1 = (const float*)d_in[8];
    const float* w_fc  = (const float*)d_in[9];
    const float* b_fc  = (const float*)d_in[10];
    float* out = (float*)d_out;

    const size_t smem_bytes = SMEMF * sizeof(float);
    cudaFuncSetAttribute(lstm2_tc_v6,
                         cudaFuncAttributeMaxDynamicSharedMemorySize,
                         (int)smem_bytes);

    lstm2_tc_v6<<<NBLK, NTH, smem_bytes>>>(
        x, w_ih0, w_hh0, b_ih0, b_hh0,
        w_ih1, w_hh1, b_ih1, b_hh1,
        w_fc, b_fc, out);
}

// round 12
// speedup vs baseline: 2.4530x; 1.0628x over previous
#include <cuda_runtime.h>
#include <cstdint>

#define TSTEPS 256
#define HSZ 50
#define ISZ 7
#define EPB 32
#define NTH 512
#define NBLK 128
#define MW 7           // MMA warps; warp w owns M-tiles w and w+7 (latter if w<6)
#define K0C 8          // layer0 K chunks (K=64: 50 h + 7 x + 7 zero)
#define K1C 13         // layer1 K chunks (K=104: 50 h0 + 50 h1 + 4 zero)
#define SG 36          // gates buffer row stride
#define S0 68          // hT0 row stride (32 rows x 68)
#define S1 108         // hT1 / Wsm1 row stride
#define SA 68          // A0 smem tile stride

// smem float offsets
#define OFF_W1 0                   // [208][108] = 22464
#define OFF_G  22464               // [208][36]  = 7488
#define OFF_T0 29952               // [32][68]   = 2176
#define OFF_T1 32128               // [32][108]  = 3456
#define OFF_B0 35584               // [208]
#define OFF_B1 35792               // [208]
#define OFF_A0 36000               // [96][68]   = 6528 (layer0 A rows 112..207)
#define SMEMF  42528               // 170112 bytes

__device__ __forceinline__ float sigm(float v) {
    return __fdividef(1.f, 1.f + __expf(-v));
}
__device__ __forceinline__ float tanh_f(float v) {
    return __fdividef(2.f, 1.f + __expf(-2.f * v)) - 1.f;
}
__device__ __forceinline__ uint32_t tf32u(float f) {
    uint32_t u; asm("cvt.rna.tf32.f32 %0, %1;" : "=r"(u) : "f"(f)); return u;
}
__device__ __forceinline__ float tf32f(float f) {
    return __uint_as_float(tf32u(f));
}
__device__ __forceinline__ void mma_tf32(float d[4], const uint32_t a[4],
                                         uint32_t b0, uint32_t b1) {
    asm volatile(
        "mma.sync.aligned.m16n8k8.row.col.f32.tf32.tf32.f32 "
        "{%0,%1,%2,%3}, {%4,%5,%6,%7}, {%8,%9}, {%0,%1,%2,%3};"
        : "+f"(d[0]), "+f"(d[1]), "+f"(d[2]), "+f"(d[3])
        : "r"(a[0]), "r"(a[1]), "r"(a[2]), "r"(a[3]), "r"(b0), "r"(b1));
}

// layer0 A element (gate-row r in [j][i,f,g,o] order, col c over [h(50)|x(7)|0])
__device__ __forceinline__ float w0val(const float* __restrict__ wih0,
                                       const float* __restrict__ whh0,
                                       int r, int c) {
    if (r >= 200) return 0.f;
    const int j = r >> 2, gi = r & 3;
    if (c < 50) return whh0[(gi * 50 + j) * 50 + c];
    if (c < 57) return wih0[(gi * 50 + j) * 7 + (c - 50)];
    return 0.f;
}

__global__ __launch_bounds__(NTH, 1)
void lstm2_tc_v7(const float* __restrict__ x,
                 const float* __restrict__ w_ih0, const float* __restrict__ w_hh0,
                 const float* __restrict__ b_ih0, const float* __restrict__ b_hh0,
                 const float* __restrict__ w_ih1, const float* __restrict__ w_hh1,
                 const float* __restrict__ b_ih1, const float* __restrict__ b_hh1,
                 const float* __restrict__ w_fc,  const float* __restrict__ b_fc,
                 float* __restrict__ out)
{
    extern __shared__ float sm[];
    const int tid  = threadIdx.x;
    const int blk  = blockIdx.x;
    const int wid  = tid >> 5;
    const int lane = tid & 31;
    const int gid  = lane >> 2;     // groupID 0..7
    const int t4   = lane & 3;      // threadID in group

    // ---- stage layer1 weights [208][104] (tf32) ----
    for (int i = tid; i < 208 * 104; i += NTH) {
        const int r = i / 104, k = i % 104;
        float v = 0.f;
        if (r < 200) {
            const int j = r >> 2, gi = r & 3;
            if (k < 50)       v = w_ih1[(gi * 50 + j) * 50 + k];
            else if (k < 100) v = w_hh1[(gi * 50 + j) * 50 + (k - 50)];
        }
        sm[OFF_W1 + r * S1 + k] = tf32f(v);
    }
    // layer0 A for tiles 7..12 (gate rows 112..207) into smem
    for (int i = tid; i < 96 * 64; i += NTH) {
        const int r = i >> 6, k = i & 63;
        sm[OFF_A0 + r * SA + k] = tf32f(w0val(w_ih0, w_hh0, 112 + r, k));
    }
    // biases (fp32, accumulator init)
    for (int i = tid; i < 208; i += NTH) {
        float v0 = 0.f, v1 = 0.f;
        if (i < 200) {
            const int j = i >> 2, gi = i & 3;
            v0 = b_ih0[gi * 50 + j] + b_hh0[gi * 50 + j];
            v1 = b_ih1[gi * 50 + j] + b_hh1[gi * 50 + j];
        }
        sm[OFF_B0 + i] = v0;
        sm[OFF_B1 + i] = v1;
    }
    // zero operand buffers
    for (int i = tid; i < 32 * S0; i += NTH) sm[OFF_T0 + i] = 0.f;
    for (int i = tid; i < 32 * S1; i += NTH) sm[OFF_T1 + i] = 0.f;
    __syncthreads();
    // x(t=0) into hT0 cols 50..56
    if (tid < 224) {
        const int e = tid / 7, kx = tid % 7;
        sm[OFF_T0 + e * S0 + 50 + kx] =
            tf32f(x[(size_t)(blk * EPB + e) * (TSTEPS * ISZ) + kx]);
    }
    __syncthreads();

    // ---- layer0 A-fragments for tile A (rows wid*16..) resident in registers ----
    const int MA = wid * 16;
    const int MB = (wid + MW) * 16;      // second tile rows (wid<6)
    const bool hasB = (wid < MW - 1);    // warps 0..5 have a second tile
    uint32_t wa0[K0C][4];
    if (wid < MW) {
        const int r0 = MA + gid, r1 = r0 + 8;
        #pragma unroll
        for (int kc = 0; kc < K0C; kc++) {
            const int c0 = kc * 8 + t4, c1 = c0 + 4;
            wa0[kc][0] = tf32u(w0val(w_ih0, w_hh0, r0, c0));
            wa0[kc][1] = tf32u(w0val(w_ih0, w_hh0, r1, c0));
            wa0[kc][2] = tf32u(w0val(w_ih0, w_hh0, r0, c1));
            wa0[kc][3] = tf32u(w0val(w_ih0, w_hh0, r1, c1));
        }
    }

    // activation thread mapping: tid<400 -> (j = tid>>3, g = tid&7) owns elems 4g..4g+3
    const int jj = tid >> 3;
    const int gg = tid & 7;
    float c0s[4] = {0.f, 0.f, 0.f, 0.f};
    float c1s[4] = {0.f, 0.f, 0.f, 0.f};

    const float* xp = x;
    if (tid < 224)
        xp = x + (size_t)(blk * EPB + tid / 7) * (TSTEPS * ISZ) + (tid % 7);

    for (int t = 0; t < TSTEPS; t++) {
        float xv = 0.f;
        if (tid < 224 && t + 1 < TSTEPS) xv = xp[(t + 1) * ISZ];

        // ============ MMA layer 0 (two M-tiles per warp, B loaded once) ============
        if (wid < MW) {
            float accA[4][4], accB[4][4];
            {
                const float al = sm[OFF_B0 + MA + gid];
                const float ah = sm[OFF_B0 + MA + 8 + gid];
                const float bl = hasB ? sm[OFF_B0 + MB + gid] : 0.f;
                const float bh = hasB ? sm[OFF_B0 + MB + 8 + gid] : 0.f;
                #pragma unroll
                for (int n = 0; n < 4; n++) {
                    accA[n][0] = al; accA[n][1] = al; accA[n][2] = ah; accA[n][3] = ah;
                    accB[n][0] = bl; accB[n][1] = bl; accB[n][2] = bh; accB[n][3] = bh;
                }
            }
            #pragma unroll
            for (int kc = 0; kc < K0C; kc++) {
                uint32_t aB[4] = {0u, 0u, 0u, 0u};
                if (hasB) {
                    // tile B rows are A0 smem local rows wid*16 + (gid, gid+8)
                    const float* ap = sm + OFF_A0 + (wid * 16 + gid) * SA + kc * 8 + t4;
                    aB[0] = __float_as_uint(ap[0]);
                    aB[1] = __float_as_uint(ap[8 * SA]);
                    aB[2] = __float_as_uint(ap[4]);
                    aB[3] = __float_as_uint(ap[8 * SA + 4]);
                }
                #pragma unroll
                for (int n = 0; n < 4; n++) {
                    const float* bp = sm + OFF_T0 + (n * 8 + gid) * S0 + kc * 8 + t4;
                    const uint32_t b0 = __float_as_uint(bp[0]);
                    const uint32_t b1 = __float_as_uint(bp[4]);
                    mma_tf32(accA[n], wa0[kc], b0, b1);
                    if (hasB) mma_tf32(accB[n], aB, b0, b1);
                }
            }
            #pragma unroll
            for (int n = 0; n < 4; n++) {
                *reinterpret_cast<float2*>(sm + OFF_G + (MA + gid) * SG + n * 8 + t4 * 2) =
                    make_float2(accA[n][0], accA[n][1]);
                *reinterpret_cast<float2*>(sm + OFF_G + (MA + 8 + gid) * SG + n * 8 + t4 * 2) =
                    make_float2(accA[n][2], accA[n][3]);
                if (hasB) {
                    *reinterpret_cast<float2*>(sm + OFF_G + (MB + gid) * SG + n * 8 + t4 * 2) =
                        make_float2(accB[n][0], accB[n][1]);
                    *reinterpret_cast<float2*>(sm + OFF_G + (MB + 8 + gid) * SG + n * 8 + t4 * 2) =
                        make_float2(accB[n][2], accB[n][3]);
                }
            }
        }
        __syncthreads();

        // ============ activation layer 0 ============
        if (tid < 400) {
            const float* gb = sm + OFF_G + (jj * 4) * SG + gg * 4;
            const float4 vi = *reinterpret_cast<const float4*>(gb);
            const float4 vf = *reinterpret_cast<const float4*>(gb + SG);
            const float4 vg = *reinterpret_cast<const float4*>(gb + 2 * SG);
            const float4 vo = *reinterpret_cast<const float4*>(gb + 3 * SG);
            float hv[4];
            {
                const float* iv = &vi.x; const float* fv = &vf.x;
                const float* gv = &vg.x; const float* ov = &vo.x;
                #pragma unroll
                for (int e = 0; e < 4; e++) {
                    c0s[e] = sigm(fv[e]) * c0s[e] + sigm(iv[e]) * tanh_f(gv[e]);
                    hv[e]  = sigm(ov[e]) * tanh_f(c0s[e]);
                }
            }
            #pragma unroll
            for (int e = 0; e < 4; e++) {
                const float ht = tf32f(hv[e]);
                sm[OFF_T0 + (gg * 4 + e) * S0 + jj] = ht;   // layer0 h for t+1
                sm[OFF_T1 + (gg * 4 + e) * S1 + jj] = ht;   // layer1 input rows 0-49
            }
        }
        if (tid < 224) sm[OFF_T0 + (tid / 7) * S0 + 50 + tid % 7] = tf32f(xv);
        __syncthreads();

        // ============ MMA layer 1 (two M-tiles per warp, B loaded once) ============
        if (wid < MW) {
            float accA[4][4], accB[4][4];
            {
                const float al = sm[OFF_B1 + MA + gid];
                const float ah = sm[OFF_B1 + MA + 8 + gid];
                const float bl = hasB ? sm[OFF_B1 + MB + gid] : 0.f;
                const float bh = hasB ? sm[OFF_B1 + MB + 8 + gid] : 0.f;
                #pragma unroll
                for (int n = 0; n < 4; n++) {
                    accA[n][0] = al; accA[n][1] = al; accA[n][2] = ah; accA[n][3] = ah;
                    accB[n][0] = bl; accB[n][1] = bl; accB[n][2] = bh; accB[n][3] = bh;
                }
            }
            #pragma unroll
            for (int kc = 0; kc < K1C; kc++) {
                uint32_t aA[4], aB[4] = {0u, 0u, 0u, 0u};
                {
                    const float* ap = sm + OFF_W1 + (MA + gid) * S1 + kc * 8 + t4;
                    aA[0] = __float_as_uint(ap[0]);
                    aA[1] = __float_as_uint(ap[8 * S1]);
                    aA[2] = __float_as_uint(ap[4]);
                    aA[3] = __float_as_uint(ap[8 * S1 + 4]);
                }
                if (hasB) {
                    const float* ap = sm + OFF_W1 + (MB + gid) * S1 + kc * 8 + t4;
                    aB[0] = __float_as_uint(ap[0]);
                    aB[1] = __float_as_uint(ap[8 * S1]);
                    aB[2] = __float_as_uint(ap[4]);
                    aB[3] = __float_as_uint(ap[8 * S1 + 4]);
                }
                #pragma unroll
                for (int n = 0; n < 4; n++) {
                    const float* bp = sm + OFF_T1 + (n * 8 + gid) * S1 + kc * 8 + t4;
                    const uint32_t b0 = __float_as_uint(bp[0]);
                    const uint32_t b1 = __float_as_uint(bp[4]);
                    mma_tf32(accA[n], aA, b0, b1);
                    if (hasB) mma_tf32(accB[n], aB, b0, b1);
                }
            }
            #pragma unroll
            for (int n = 0; n < 4; n++) {
                *reinterpret_cast<float2*>(sm + OFF_G + (MA + gid) * SG + n * 8 + t4 * 2) =
                    make_float2(accA[n][0], accA[n][1]);
                *reinterpret_cast<float2*>(sm + OFF_G + (MA + 8 + gid) * SG + n * 8 + t4 * 2) =
                    make_float2(accA[n][2], accA[n][3]);
                if (hasB) {
                    *reinterpret_cast<float2*>(sm + OFF_G + (MB + gid) * SG + n * 8 + t4 * 2) =
                        make_float2(accB[n][0], accB[n][1]);
                    *reinterpret_cast<float2*>(sm + OFF_G + (MB + 8 + gid) * SG + n * 8 + t4 * 2) =
                        make_float2(accB[n][2], accB[n][3]);
                }
            }
        }
        __syncthreads();

        // ============ activation layer 1 ============
        if (tid < 400) {
            const float* gb = sm + OFF_G + (jj * 4) * SG + gg * 4;
            const float4 vi = *reinterpret_cast<const float4*>(gb);
            const float4 vf = *reinterpret_cast<const float4*>(gb + SG);
            const float4 vg = *reinterpret_cast<const float4*>(gb + 2 * SG);
            const float4 vo = *reinterpret_cast<const float4*>(gb + 3 * SG);
            const float* iv = &vi.x; const float* fv = &vf.x;
            const float* gv = &vg.x; const float* ov = &vo.x;
            #pragma unroll
            for (int e = 0; e < 4; e++) {
                c1s[e] = sigm(fv[e]) * c1s[e] + sigm(iv[e]) * tanh_f(gv[e]);
                const float h1 = sigm(ov[e]) * tanh_f(c1s[e]);
                sm[OFF_T1 + (gg * 4 + e) * S1 + 50 + jj] = tf32f(h1);  // rows 50-99 for t+1
            }
        }
        __syncthreads();
    }

    // ---- FC head: out[e][i] = b_fc[i] + sum_k w_fc[i][k] * h1[e][k] ----
    if (tid < 224) {
        const int i = tid % 7, e = tid / 7;
        float s = b_fc[i];
        #pragma unroll 10
        for (int k = 0; k < HSZ; k++)
            s = fmaf(w_fc[i * 50 + k], sm[OFF_T1 + e * S1 + 50 + k], s);
        out[(size_t)(blk * EPB + e) * ISZ + i] = s;
    }
}

extern "C" void kernel_launch(void* const* d_in, const int* in_sizes, int n_in,
                              void* d_out, int out_size)
{
    const float* x     = (const float*)d_in[0];
    const float* w_ih0 = (const float*)d_in[1];
    const float* w_hh0 = (const float*)d_in[2];
    const float* b_ih0 = (const float*)d_in[3];
    const float* b_hh0 = (const float*)d_in[4];
    const float* w_ih1 = (const float*)d_in[5];
    const float* w_hh1 = (const float*)d_in[6];
    const float* b_ih1 = (const float*)d_in[7];
    const float* b_hh1 = (const float*)d_in[8];
    const float* w_fc  = (const float*)d_in[9];
    const float* b_fc  = (const float*)d_in[10];
    float* out = (float*)d_out;

    const size_t smem_bytes = SMEMF * sizeof(float);
    cudaFuncSetAttribute(lstm2_tc_v7,
                         cudaFuncAttributeMaxDynamicSharedMemorySize,
                         (int)smem_bytes);

    lstm2_tc_v7<<<NBLK, NTH, smem_bytes>>>(
        x, w_ih0, w_hh0, b_ih0, b_hh0,
        w_ih1, w_hh1, b_ih1, b_hh1,
        w_fc, b_fc, out);
}